// round 10
// baseline (speedup 1.0000x reference)
#include <cuda_runtime.h>
#include <cuda_bf16.h>
#include <cstdint>

// ============================================================================
// out_f32[m, n] = f32( bf16(sum_k bf16(x[m,k]) * (bf16(w_fp8[n,k])*bf16(sc[n]))) + bf16(bias[n]) )
// M = B*S = 4096, N = OUT = 4096, K = IN = 4096. OUTPUT IS FP32.
// (1) convert x -> bf16 scratch, (2) dequantize w -> bf16 scratch,
// (3) tcgen05 bf16 GEMM, 128x128 tiles, SS mode, 3-stage cp.async pipeline
//     with LAG-1 MMA completion (commit to mbar[c%3], wait only before buffer
//     reuse) so MMA overlaps the next iteration's load/sync work.
// tcgen05 only in the arch-specific pass; generic pass gets a scalar fallback.
// ============================================================================

#if defined(__CUDA_ARCH__) && \
    (defined(__CUDA_ARCH_FEAT_SM103_ALL) || defined(__CUDA_ARCH_FEAT_SM100_ALL) || \
     defined(__CUDA_ARCH_FEAT_SM101_ALL) || defined(__CUDA_ARCH_SPECIFIC__) || \
     defined(__CUDA_ARCH_FAMILY_SPECIFIC__))
#define HAS_TCGEN05 1
#else
#define HAS_TCGEN05 0
#endif

static constexpr int Mdim = 4096, Ndim = 4096, Kdim = 4096;
static constexpr int MT = 128, NT = 128, KC = 64;        // tile sizes; KC=64 bf16=128B
static constexpr int STAGES = 3;
static constexpr int NCHUNK = Kdim / KC;                  // 64
static constexpr int STAGE_BYTES = 128 * 128;             // 128 rows x 128B

static constexpr int SMEM_TMEM_PTR = 0;
static constexpr int SMEM_MBAR = 64;                      // 3 x 8B mbarriers
static constexpr int SMEM_A = 1024;
static constexpr int SMEM_B = SMEM_A + STAGES * STAGE_BYTES;
static constexpr int SMEM_TOTAL = SMEM_B + STAGES * STAGE_BYTES;  // ~99.3 KB -> 2 CTAs/SM

// idesc kind::f16, single N=128 dispatch (proven correct in R6-R8):
// dtype=F32(1<<4), atype=BF16(1<<7), btype=BF16(1<<10), N>>3@[17], M>>4@[24]
static constexpr uint32_t IDESC =
    (1u << 4) | (1u << 7) | (1u << 10) | ((NT / 8) << 17) | ((MT / 16) << 24);

// bf16 scratch (allowed: __device__ global arrays)
__device__ __nv_bfloat16 g_x[(size_t)Mdim * Kdim];
__device__ __nv_bfloat16 g_w[(size_t)Ndim * Kdim];

// ============================================================================
// PTX helpers
// ============================================================================

__device__ __forceinline__ uint32_t smem_u32(const void* p) {
    uint32_t a;
    asm("{ .reg .u64 t; cvta.to.shared.u64 t, %1; cvt.u32.u64 %0, t; }"
        : "=r"(a) : "l"(p));
    return a;
}

__device__ __forceinline__ void cp_async16(uint32_t s, const void* g) {
    asm volatile("cp.async.cg.shared.global [%0], [%1], 16;" :: "r"(s), "l"(g));
}
__device__ __forceinline__ void cp_commit() {
    asm volatile("cp.async.commit_group;" ::: "memory");
}
template <int N>
__device__ __forceinline__ void cp_wait() {
    asm volatile("cp.async.wait_group %0;" :: "n"(N) : "memory");
}

#if HAS_TCGEN05
__device__ __forceinline__ uint32_t elect_one() {
    uint32_t pred;
    asm volatile(
        "{\n\t.reg .pred p;\n\t"
        "elect.sync _|p, 0xFFFFFFFF;\n\t"
        "selp.b32 %0, 1, 0, p;\n\t}"
        : "=r"(pred));
    return pred;
}

__device__ __forceinline__ void mbar_init(uint32_t addr, uint32_t count) {
    asm volatile("mbarrier.init.shared.b64 [%0], %1;" :: "r"(addr), "r"(count) : "memory");
}
__device__ __forceinline__ void mbar_inval(uint32_t addr) {
    asm volatile("mbarrier.inval.shared.b64 [%0];" :: "r"(addr) : "memory");
}
__device__ __forceinline__ void mbar_wait(uint32_t addr, uint32_t parity) {
    asm volatile(
        "{\n\t.reg .pred P;\n\t"
        "WAIT_%=:\n\t"
        "mbarrier.try_wait.parity.acquire.cta.shared::cta.b64 P, [%0], %1, 0x989680;\n\t"
        "@P bra DONE_%=;\n\t"
        "bra WAIT_%=;\n\t"
        "DONE_%=:\n\t}"
        :: "r"(addr), "r"(parity) : "memory");
}

__device__ __forceinline__ void fence_proxy_async_cta() {
    asm volatile("fence.proxy.async.shared::cta;" ::: "memory");
}

// SW128 K-major descriptor: layout=2, version=1, SBO=64, LBO=1
__device__ __forceinline__ uint64_t make_desc(uint32_t addr) {
    const uint64_t base =
        (uint64_t(2) << 61) | (uint64_t(1) << 46) | (uint64_t(64) << 32) | (uint64_t(1) << 16);
    return base | ((uint64_t)(addr >> 4) & 0x3FFF);
}

__device__ __forceinline__ void mma_f16_ss(uint32_t d_tmem, uint64_t a_desc, uint64_t b_desc,
                                           uint32_t idesc, uint32_t enable) {
    uint32_t zero = 0;
    asm volatile(
        "{\n\t.reg .pred p;\n\t"
        "setp.ne.u32 p, %4, 0;\n\t"
        "tcgen05.mma.cta_group::1.kind::f16 [%0], %1, %2, %3, {%5, %5, %5, %5}, p;\n\t}"
        :: "r"(d_tmem), "l"(a_desc), "l"(b_desc), "r"(idesc), "r"(enable), "r"(zero)
        : "memory");
}

__device__ __forceinline__ void tc_commit(uint32_t mbar) {
    asm volatile(
        "tcgen05.commit.cta_group::1.mbarrier::arrive::one.shared::cluster.b64 [%0];"
        :: "r"(mbar) : "memory");
}

#define TC_ALLOC(smem_addr, ncols) \
    asm volatile("tcgen05.alloc.cta_group::1.sync.aligned.shared::cta.b32 [%0], %1;" \
                 :: "r"(smem_addr), "r"((uint32_t)(ncols)) : "memory")
#define TC_DEALLOC(tmem, ncols) \
    asm volatile("tcgen05.dealloc.cta_group::1.sync.aligned.b32 %0, %1;" \
                 :: "r"(tmem), "r"((uint32_t)(ncols)))
#define TC_RELINQUISH() \
    asm volatile("tcgen05.relinquish_alloc_permit.cta_group::1.sync.aligned;")
#define TC_FENCE_AFTER() asm volatile("tcgen05.fence::after_thread_sync;" ::: "memory")
#define TC_WAIT_LD() asm volatile("tcgen05.wait::ld.sync.aligned;" ::: "memory")

#define LDTM_X32(r, addr) \
    asm volatile( \
        "tcgen05.ld.sync.aligned.32x32b.x32.b32 " \
        "{%0, %1, %2, %3, %4, %5, %6, %7, " \
        " %8, %9, %10, %11, %12, %13, %14, %15, " \
        " %16, %17, %18, %19, %20, %21, %22, %23, " \
        " %24, %25, %26, %27, %28, %29, %30, %31}, [%32];" \
        : "=r"((r)[0]),  "=r"((r)[1]),  "=r"((r)[2]),  "=r"((r)[3]), \
          "=r"((r)[4]),  "=r"((r)[5]),  "=r"((r)[6]),  "=r"((r)[7]), \
          "=r"((r)[8]),  "=r"((r)[9]),  "=r"((r)[10]), "=r"((r)[11]), \
          "=r"((r)[12]), "=r"((r)[13]), "=r"((r)[14]), "=r"((r)[15]), \
          "=r"((r)[16]), "=r"((r)[17]), "=r"((r)[18]), "=r"((r)[19]), \
          "=r"((r)[20]), "=r"((r)[21]), "=r"((r)[22]), "=r"((r)[23]), \
          "=r"((r)[24]), "=r"((r)[25]), "=r"((r)[26]), "=r"((r)[27]), \
          "=r"((r)[28]), "=r"((r)[29]), "=r"((r)[30]), "=r"((r)[31]) \
        : "r"(addr))
#endif  // HAS_TCGEN05

// ============================================================================
// Conversion kernels (arch-neutral)
// ============================================================================

__global__ void __launch_bounds__(256) cvt_x_kernel(const float* __restrict__ x) {
    size_t i = ((size_t)blockIdx.x * blockDim.x + threadIdx.x) * 4;
    float4 v = *reinterpret_cast<const float4*>(x + i);
    *reinterpret_cast<__nv_bfloat162*>(&g_x[i])     = __floats2bfloat162_rn(v.x, v.y);
    *reinterpret_cast<__nv_bfloat162*>(&g_x[i + 2]) = __floats2bfloat162_rn(v.z, v.w);
}

__global__ void __launch_bounds__(256) cvt_w_kernel(const float* __restrict__ wq,
                                                    const float* __restrict__ sc) {
    size_t i = ((size_t)blockIdx.x * blockDim.x + threadIdx.x) * 4;
    int o = (int)(i >> 12);  // row = i / 4096
    __nv_bfloat16 s = __float2bfloat16(sc[o]);
    float4 v = *reinterpret_cast<const float4*>(wq + i);
    __nv_bfloat16 h0 = __hmul(__float2bfloat16(v.x), s);
    __nv_bfloat16 h1 = __hmul(__float2bfloat16(v.y), s);
    __nv_bfloat16 h2 = __hmul(__float2bfloat16(v.z), s);
    __nv_bfloat16 h3 = __hmul(__float2bfloat16(v.w), s);
    *reinterpret_cast<__nv_bfloat162*>(&g_w[i])     = __halves2bfloat162(h0, h1);
    *reinterpret_cast<__nv_bfloat162*>(&g_w[i + 2]) = __halves2bfloat162(h2, h3);
}

// ============================================================================
// GEMM kernel: 128x128 tile per CTA, SS mode, lag-1 pipelined MMA, FP32 out.
// ============================================================================

__global__ void __launch_bounds__(128) gemm_kernel(float* __restrict__ out,
                                                   const float* __restrict__ bias) {
    extern __shared__ char smem[];
    int tid = threadIdx.x;
    int n0 = blockIdx.x * NT;
    int m0 = blockIdx.y * MT;

#if HAS_TCGEN05
    uint32_t sb = smem_u32(smem);
    int wid = tid >> 5;
    int lid = tid & 31;

    if (tid == 0) {
        #pragma unroll
        for (int s = 0; s < STAGES; s++) mbar_init(sb + SMEM_MBAR + 8 * s, 1);
    }
    // ONLY warp 0 touches the TMEM allocation permit.
    if (wid == 0) {
        TC_ALLOC(sb + SMEM_TMEM_PTR, 128);
    }
    __syncthreads();
    uint32_t tmem;
    asm volatile("ld.shared.b32 %0, [%1];" : "=r"(tmem) : "r"(sb + SMEM_TMEM_PTR));

    // Thread t loads A row m0+t and B row n0+t (128B each, swizzled).
    const __nv_bfloat16* xrow = g_x + (size_t)(m0 + tid) * Kdim;
    const __nv_bfloat16* wrow = g_w + (size_t)(n0 + tid) * Kdim;
    uint32_t swoff[8];
    #pragma unroll
    for (int j = 0; j < 8; j++) {
        uint32_t off = (uint32_t)tid * 128 + j * 16;
        swoff[j] = off ^ ((off >> 3) & 0x70);
    }

    auto load_chunk = [&](int c, int s) {
        uint32_t abase = sb + SMEM_A + s * STAGE_BYTES;
        uint32_t bbase = sb + SMEM_B + s * STAGE_BYTES;
        const __nv_bfloat16* xa = xrow + c * KC;
        const __nv_bfloat16* wb = wrow + c * KC;
        #pragma unroll
        for (int j = 0; j < 8; j++) {
            cp_async16(abase + swoff[j], xa + j * 8);
            cp_async16(bbase + swoff[j], wb + j * 8);
        }
        cp_commit();
    };

    // Prologue: prefetch chunks 0 and 1.
    load_chunk(0, 0);
    load_chunk(1, 1);

    for (int c = 0; c < NCHUNK; c++) {
        int buf = c % STAGES;

        // Prefetch chunk c+2 into buffer (c+2)%3 == (c-1)%3. Before overwriting
        // it, wait for chunk c-1's MMA commit (lag-1: chunk c's MMA from the
        // previous iteration keeps running underneath).
        if (c + 2 < NCHUNK) {
            if (c >= 1) {
                mbar_wait(sb + SMEM_MBAR + 8 * ((c - 1) % STAGES), ((c - 1) / STAGES) & 1);
            }
            load_chunk(c + 2, (c + 2) % STAGES);
        }

        // Wait for chunk c's cp.async group (2 newer groups may be pending).
        int rem = NCHUNK - 1 - c;
        if (rem >= 2)      cp_wait<2>();
        else if (rem == 1) cp_wait<1>();
        else               cp_wait<0>();
        fence_proxy_async_cta();
        __syncthreads();

        // Issue chunk c's MMAs and commit to mbar[c%3]. NO completion wait here.
        if (wid == 0) {
            TC_FENCE_AFTER();
            uint64_t ad = make_desc(sb + SMEM_A + buf * STAGE_BYTES);
            uint64_t bd = make_desc(sb + SMEM_B + buf * STAGE_BYTES);
            if (elect_one()) {
                #pragma unroll
                for (int kk = 0; kk < 4; kk++) {
                    // K-step: 16 bf16 = 32B = 2 descriptor units. N=128 single atom.
                    mma_f16_ss(tmem, ad + kk * 2, bd + kk * 2, IDESC,
                               (c == 0 && kk == 0) ? 0u : 1u);
                }
                tc_commit(sb + SMEM_MBAR + 8 * buf);
            }
        }
    }

    // Final commit (chunk NCHUNK-1) tracks all prior MMAs.
    mbar_wait(sb + SMEM_MBAR + 8 * ((NCHUNK - 1) % STAGES), ((NCHUNK - 1) / STAGES) & 1);
    TC_FENCE_AFTER();

    // Epilogue (FP32 OUTPUT): warp reads its 32-lane subpartition (row =
    // wid*32+lid). Reference semantics: bf16(acc) + bf16(bias) in bf16 -> f32.
    {
        int mrow = m0 + wid * 32 + lid;
        float* orow = out + (size_t)mrow * Ndim + n0;
        #pragma unroll
        for (int cb = 0; cb < NT; cb += 32) {
            uint32_t r[32];
            LDTM_X32(r, tmem + cb);
            TC_WAIT_LD();
            float vals[32];
            #pragma unroll
            for (int j = 0; j < 32; j++) {
                __nv_bfloat16 s = __hadd(__float2bfloat16(__uint_as_float(r[j])),
                                         __float2bfloat16(bias[n0 + cb + j]));
                vals[j] = __bfloat162float(s);
            }
            float4* dst = reinterpret_cast<float4*>(orow + cb);
            #pragma unroll
            for (int q = 0; q < 8; q++) {
                dst[q] = make_float4(vals[4 * q], vals[4 * q + 1],
                                     vals[4 * q + 2], vals[4 * q + 3]);
            }
        }
    }

    __syncthreads();
    if (tid == 0) {
        #pragma unroll
        for (int s = 0; s < STAGES; s++) mbar_inval(sb + SMEM_MBAR + 8 * s);
    }
    __syncthreads();
    if (wid == 0) {
        TC_RELINQUISH();
        TC_DEALLOC(tmem, 128);
    }
#else
    // ---------- Generic fallback (no tcgen05 in this compile pass) ----------
    __nv_bfloat16* As = reinterpret_cast<__nv_bfloat16*>(smem);            // 128 x 32
    __nv_bfloat16* Bs = As + 128 * 32;                                     // 128 x 32
    int tr = tid >> 3;   // 0..15 -> rows [tr*8, tr*8+8)
    int tc = tid & 7;    // 0..7  -> cols [tc*16, tc*16+16)

    float acc[8][16];
    #pragma unroll
    for (int i = 0; i < 8; i++)
        #pragma unroll
        for (int j = 0; j < 16; j++) acc[i][j] = 0.0f;

    for (int kc = 0; kc < Kdim; kc += 32) {
        const uint4* srcA = reinterpret_cast<const uint4*>(g_x + (size_t)(m0 + tid) * Kdim + kc);
        const uint4* srcB = reinterpret_cast<const uint4*>(g_w + (size_t)(n0 + tid) * Kdim + kc);
        uint4* dA = reinterpret_cast<uint4*>(As + tid * 32);
        uint4* dB = reinterpret_cast<uint4*>(Bs + tid * 32);
        #pragma unroll
        for (int j = 0; j < 4; j++) { dA[j] = srcA[j]; dB[j] = srcB[j]; }
        __syncthreads();

        for (int kk = 0; kk < 32; kk++) {
            float a[8], b[16];
            #pragma unroll
            for (int i = 0; i < 8; i++)
                a[i] = __bfloat162float(As[(tr * 8 + i) * 32 + kk]);
            #pragma unroll
            for (int j = 0; j < 16; j++)
                b[j] = __bfloat162float(Bs[(tc * 16 + j) * 32 + kk]);
            #pragma unroll
            for (int i = 0; i < 8; i++)
                #pragma unroll
                for (int j = 0; j < 16; j++)
                    acc[i][j] = fmaf(a[i], b[j], acc[i][j]);
        }
        __syncthreads();
    }

    #pragma unroll
    for (int i = 0; i < 8; i++) {
        int m = m0 + tr * 8 + i;
        #pragma unroll
        for (int j = 0; j < 16; j++) {
            int n = n0 + tc * 16 + j;
            __nv_bfloat16 v = __hadd(__float2bfloat16(acc[i][j]),
                                     __float2bfloat16(bias[n]));
            out[(size_t)m * Ndim + n] = __bfloat162float(v);
        }
    }
#endif
}

// ============================================================================
// Launch
// ============================================================================

extern "C" void kernel_launch(void* const* d_in, const int* in_sizes, int n_in,
                              void* d_out, int out_size) {
    const float* x    = (const float*)d_in[0];   // [B, S, IN] f32
    const float* wq   = (const float*)d_in[1];   // [OUT, IN] f32 (fp8-representable)
    const float* ws   = (const float*)d_in[2];   // [OUT, 1] f32
    const float* bias = (const float*)d_in[3];   // [OUT] f32
    float* out = (float*)d_out;                  // [B, S, OUT] FP32

    // Convert inputs to bf16 scratch.
    {
        int threads = 256;
        int blocks = (Mdim * Kdim / 4) / threads;  // 16384
        cvt_x_kernel<<<blocks, threads>>>(x);
        cvt_w_kernel<<<blocks, threads>>>(wq, ws);
    }

    cudaFuncSetAttribute(gemm_kernel, cudaFuncAttributeMaxDynamicSharedMemorySize, SMEM_TOTAL);
    dim3 grid(Ndim / NT, Mdim / MT);  // (32, 32)
    gemm_kernel<<<grid, 128, SMEM_TOTAL>>>(out, bias);
}

// round 11
// speedup vs baseline: 2.5104x; 2.5104x over previous
#include <cuda_runtime.h>
#include <cuda_bf16.h>
#include <cstdint>

// ============================================================================
// out_f32[m, n] = f32( bf16(sum_k bf16(x[m,k]) * (bf16(w_fp8[n,k])*bf16(sc[n]))) + bf16(bias[n]) )
// M = B*S = 4096, N = OUT = 4096, K = IN = 4096. OUTPUT IS FP32.
// (1) convert x -> bf16 scratch, (2) dequantize w -> bf16 scratch,
// (3) tcgen05 bf16 GEMM, 128x128 tiles, SS mode, 3-stage cp.async pipeline,
//     lag-1 MMA completion, COALESCED loads (8 lanes per row -> 4 contiguous
//     128B lines per warp instruction instead of 32 scattered ones; R10 was
//     L1tex-wavefront-bound at ~2048 cyc/chunk from the per-thread-row map).
// tcgen05 only in the arch-specific pass; generic pass gets a scalar fallback.
// ============================================================================

#if defined(__CUDA_ARCH__) && \
    (defined(__CUDA_ARCH_FEAT_SM103_ALL) || defined(__CUDA_ARCH_FEAT_SM100_ALL) || \
     defined(__CUDA_ARCH_FEAT_SM101_ALL) || defined(__CUDA_ARCH_SPECIFIC__) || \
     defined(__CUDA_ARCH_FAMILY_SPECIFIC__))
#define HAS_TCGEN05 1
#else
#define HAS_TCGEN05 0
#endif

static constexpr int Mdim = 4096, Ndim = 4096, Kdim = 4096;
static constexpr int MT = 128, NT = 128, KC = 64;        // tile sizes; KC=64 bf16=128B
static constexpr int STAGES = 3;
static constexpr int NCHUNK = Kdim / KC;                  // 64
static constexpr int STAGE_BYTES = 128 * 128;             // 128 rows x 128B

static constexpr int SMEM_TMEM_PTR = 0;
static constexpr int SMEM_MBAR = 64;                      // 3 x 8B mbarriers
static constexpr int SMEM_A = 1024;
static constexpr int SMEM_B = SMEM_A + STAGES * STAGE_BYTES;
static constexpr int SMEM_TOTAL = SMEM_B + STAGES * STAGE_BYTES;  // ~99.3 KB -> 2 CTAs/SM

// idesc kind::f16, N=128 single dispatch (proven correct R6-R10):
// dtype=F32(1<<4), atype=BF16(1<<7), btype=BF16(1<<10), N>>3@[17], M>>4@[24]
static constexpr uint32_t IDESC =
    (1u << 4) | (1u << 7) | (1u << 10) | ((NT / 8) << 17) | ((MT / 16) << 24);

// bf16 scratch (allowed: __device__ global arrays)
__device__ __nv_bfloat16 g_x[(size_t)Mdim * Kdim];
__device__ __nv_bfloat16 g_w[(size_t)Ndim * Kdim];

// ============================================================================
// PTX helpers
// ============================================================================

__device__ __forceinline__ uint32_t smem_u32(const void* p) {
    uint32_t a;
    asm("{ .reg .u64 t; cvta.to.shared.u64 t, %1; cvt.u32.u64 %0, t; }"
        : "=r"(a) : "l"(p));
    return a;
}

__device__ __forceinline__ void cp_async16(uint32_t s, const void* g) {
    asm volatile("cp.async.cg.shared.global [%0], [%1], 16;" :: "r"(s), "l"(g));
}
__device__ __forceinline__ void cp_commit() {
    asm volatile("cp.async.commit_group;" ::: "memory");
}
template <int N>
__device__ __forceinline__ void cp_wait() {
    asm volatile("cp.async.wait_group %0;" :: "n"(N) : "memory");
}

#if HAS_TCGEN05
__device__ __forceinline__ uint32_t elect_one() {
    uint32_t pred;
    asm volatile(
        "{\n\t.reg .pred p;\n\t"
        "elect.sync _|p, 0xFFFFFFFF;\n\t"
        "selp.b32 %0, 1, 0, p;\n\t}"
        : "=r"(pred));
    return pred;
}

__device__ __forceinline__ void mbar_init(uint32_t addr, uint32_t count) {
    asm volatile("mbarrier.init.shared.b64 [%0], %1;" :: "r"(addr), "r"(count) : "memory");
}
__device__ __forceinline__ void mbar_inval(uint32_t addr) {
    asm volatile("mbarrier.inval.shared.b64 [%0];" :: "r"(addr) : "memory");
}
__device__ __forceinline__ void mbar_wait(uint32_t addr, uint32_t parity) {
    asm volatile(
        "{\n\t.reg .pred P;\n\t"
        "WAIT_%=:\n\t"
        "mbarrier.try_wait.parity.acquire.cta.shared::cta.b64 P, [%0], %1, 0x989680;\n\t"
        "@P bra DONE_%=;\n\t"
        "bra WAIT_%=;\n\t"
        "DONE_%=:\n\t}"
        :: "r"(addr), "r"(parity) : "memory");
}

__device__ __forceinline__ void fence_proxy_async_cta() {
    asm volatile("fence.proxy.async.shared::cta;" ::: "memory");
}

// SW128 K-major descriptor: layout=2, version=1, SBO=64, LBO=1
__device__ __forceinline__ uint64_t make_desc(uint32_t addr) {
    const uint64_t base =
        (uint64_t(2) << 61) | (uint64_t(1) << 46) | (uint64_t(64) << 32) | (uint64_t(1) << 16);
    return base | ((uint64_t)(addr >> 4) & 0x3FFF);
}

__device__ __forceinline__ void mma_f16_ss(uint32_t d_tmem, uint64_t a_desc, uint64_t b_desc,
                                           uint32_t idesc, uint32_t enable) {
    uint32_t zero = 0;
    asm volatile(
        "{\n\t.reg .pred p;\n\t"
        "setp.ne.u32 p, %4, 0;\n\t"
        "tcgen05.mma.cta_group::1.kind::f16 [%0], %1, %2, %3, {%5, %5, %5, %5}, p;\n\t}"
        :: "r"(d_tmem), "l"(a_desc), "l"(b_desc), "r"(idesc), "r"(enable), "r"(zero)
        : "memory");
}

__device__ __forceinline__ void tc_commit(uint32_t mbar) {
    asm volatile(
        "tcgen05.commit.cta_group::1.mbarrier::arrive::one.shared::cluster.b64 [%0];"
        :: "r"(mbar) : "memory");
}

#define TC_ALLOC(smem_addr, ncols) \
    asm volatile("tcgen05.alloc.cta_group::1.sync.aligned.shared::cta.b32 [%0], %1;" \
                 :: "r"(smem_addr), "r"((uint32_t)(ncols)) : "memory")
#define TC_DEALLOC(tmem, ncols) \
    asm volatile("tcgen05.dealloc.cta_group::1.sync.aligned.b32 %0, %1;" \
                 :: "r"(tmem), "r"((uint32_t)(ncols)))
#define TC_RELINQUISH() \
    asm volatile("tcgen05.relinquish_alloc_permit.cta_group::1.sync.aligned;")
#define TC_FENCE_AFTER() asm volatile("tcgen05.fence::after_thread_sync;" ::: "memory")
#define TC_WAIT_LD() asm volatile("tcgen05.wait::ld.sync.aligned;" ::: "memory")

#define LDTM_X32(r, addr) \
    asm volatile( \
        "tcgen05.ld.sync.aligned.32x32b.x32.b32 " \
        "{%0, %1, %2, %3, %4, %5, %6, %7, " \
        " %8, %9, %10, %11, %12, %13, %14, %15, " \
        " %16, %17, %18, %19, %20, %21, %22, %23, " \
        " %24, %25, %26, %27, %28, %29, %30, %31}, [%32];" \
        : "=r"((r)[0]),  "=r"((r)[1]),  "=r"((r)[2]),  "=r"((r)[3]), \
          "=r"((r)[4]),  "=r"((r)[5]),  "=r"((r)[6]),  "=r"((r)[7]), \
          "=r"((r)[8]),  "=r"((r)[9]),  "=r"((r)[10]), "=r"((r)[11]), \
          "=r"((r)[12]), "=r"((r)[13]), "=r"((r)[14]), "=r"((r)[15]), \
          "=r"((r)[16]), "=r"((r)[17]), "=r"((r)[18]), "=r"((r)[19]), \
          "=r"((r)[20]), "=r"((r)[21]), "=r"((r)[22]), "=r"((r)[23]), \
          "=r"((r)[24]), "=r"((r)[25]), "=r"((r)[26]), "=r"((r)[27]), \
          "=r"((r)[28]), "=r"((r)[29]), "=r"((r)[30]), "=r"((r)[31]) \
        : "r"(addr))
#endif  // HAS_TCGEN05

// ============================================================================
// Conversion kernels (arch-neutral)
// ============================================================================

__global__ void __launch_bounds__(256) cvt_x_kernel(const float* __restrict__ x) {
    size_t i = ((size_t)blockIdx.x * blockDim.x + threadIdx.x) * 4;
    float4 v = *reinterpret_cast<const float4*>(x + i);
    *reinterpret_cast<__nv_bfloat162*>(&g_x[i])     = __floats2bfloat162_rn(v.x, v.y);
    *reinterpret_cast<__nv_bfloat162*>(&g_x[i + 2]) = __floats2bfloat162_rn(v.z, v.w);
}

__global__ void __launch_bounds__(256) cvt_w_kernel(const float* __restrict__ wq,
                                                    const float* __restrict__ sc) {
    size_t i = ((size_t)blockIdx.x * blockDim.x + threadIdx.x) * 4;
    int o = (int)(i >> 12);  // row = i / 4096
    __nv_bfloat16 s = __float2bfloat16(sc[o]);
    float4 v = *reinterpret_cast<const float4*>(wq + i);
    __nv_bfloat16 h0 = __hmul(__float2bfloat16(v.x), s);
    __nv_bfloat16 h1 = __hmul(__float2bfloat16(v.y), s);
    __nv_bfloat16 h2 = __hmul(__float2bfloat16(v.z), s);
    __nv_bfloat16 h3 = __hmul(__float2bfloat16(v.w), s);
    *reinterpret_cast<__nv_bfloat162*>(&g_w[i])     = __halves2bfloat162(h0, h1);
    *reinterpret_cast<__nv_bfloat162*>(&g_w[i + 2]) = __halves2bfloat162(h2, h3);
}

// ============================================================================
// GEMM kernel: 128x128 tile per CTA, SS mode, coalesced cp.async, lag-1 MMA.
// ============================================================================

__global__ void __launch_bounds__(128) gemm_kernel(float* __restrict__ out,
                                                   const float* __restrict__ bias) {
    extern __shared__ char smem[];
    int tid = threadIdx.x;
    int n0 = blockIdx.x * NT;
    int m0 = blockIdx.y * MT;

#if HAS_TCGEN05
    uint32_t sb = smem_u32(smem);
    int wid = tid >> 5;
    int lid = tid & 31;

    if (tid == 0) {
        #pragma unroll
        for (int s = 0; s < STAGES; s++) mbar_init(sb + SMEM_MBAR + 8 * s, 1);
    }
    // ONLY warp 0 touches the TMEM allocation permit.
    if (wid == 0) {
        TC_ALLOC(sb + SMEM_TMEM_PTR, 128);
    }
    __syncthreads();
    uint32_t tmem;
    asm volatile("ld.shared.b32 %0, [%1];" : "=r"(tmem) : "r"(sb + SMEM_TMEM_PTR));

    // COALESCED load mapping: 8 lanes cover one 128B row (lane%8 -> 16B slot),
    // pass j covers rows [j*16, j*16+16). Each warp instruction touches 4
    // contiguous 128B lines (4 wavefronts) instead of 32 scattered ones.
    int lrow = tid >> 3;                   // 0..15: row within pass
    int lcolb = (tid & 7) * 16;            // byte offset within row
    uint32_t swc[8];
    #pragma unroll
    for (int j = 0; j < 8; j++) {
        uint32_t off = (uint32_t)(lrow + j * 16) * 128 + lcolb;
        swc[j] = off ^ ((off >> 3) & 0x70);
    }
    // gmem base for this thread's slot (elements): row (m0|n0)+lrow, col (tid&7)*8
    const __nv_bfloat16* xbase = g_x + (size_t)(m0 + lrow) * Kdim + (tid & 7) * 8;
    const __nv_bfloat16* wbase = g_w + (size_t)(n0 + lrow) * Kdim + (tid & 7) * 8;

    auto load_chunk = [&](int c, int s) {
        uint32_t abase = sb + SMEM_A + s * STAGE_BYTES;
        uint32_t bbase = sb + SMEM_B + s * STAGE_BYTES;
        const __nv_bfloat16* xa = xbase + c * KC;
        const __nv_bfloat16* wb = wbase + c * KC;
        #pragma unroll
        for (int j = 0; j < 8; j++) {
            cp_async16(abase + swc[j], xa + (size_t)j * 16 * Kdim);
            cp_async16(bbase + swc[j], wb + (size_t)j * 16 * Kdim);
        }
        cp_commit();
    };

    // Prologue: prefetch chunks 0 and 1.
    load_chunk(0, 0);
    load_chunk(1, 1);

    for (int c = 0; c < NCHUNK; c++) {
        int buf = c % STAGES;

        // Prefetch chunk c+2 into buffer (c+2)%3 == (c-1)%3. Before overwriting
        // it, wait for chunk c-1's MMA commit (lag-1: chunk c's MMA keeps
        // running underneath the next iteration's work).
        if (c + 2 < NCHUNK) {
            if (c >= 1) {
                mbar_wait(sb + SMEM_MBAR + 8 * ((c - 1) % STAGES), ((c - 1) / STAGES) & 1);
            }
            load_chunk(c + 2, (c + 2) % STAGES);
        }

        // Wait for chunk c's cp.async group (2 newer groups may be pending).
        int rem = NCHUNK - 1 - c;
        if (rem >= 2)      cp_wait<2>();
        else if (rem == 1) cp_wait<1>();
        else               cp_wait<0>();
        fence_proxy_async_cta();
        __syncthreads();

        // Issue chunk c's MMAs and commit to mbar[c%3]. NO completion wait here.
        if (wid == 0) {
            TC_FENCE_AFTER();
            uint64_t ad = make_desc(sb + SMEM_A + buf * STAGE_BYTES);
            uint64_t bd = make_desc(sb + SMEM_B + buf * STAGE_BYTES);
            if (elect_one()) {
                #pragma unroll
                for (int kk = 0; kk < 4; kk++) {
                    // K-step: 16 bf16 = 32B = 2 descriptor units. N=128 atom.
                    mma_f16_ss(tmem, ad + kk * 2, bd + kk * 2, IDESC,
                               (c == 0 && kk == 0) ? 0u : 1u);
                }
                tc_commit(sb + SMEM_MBAR + 8 * buf);
            }
        }
    }

    // Final commit (chunk NCHUNK-1) tracks all prior MMAs.
    mbar_wait(sb + SMEM_MBAR + 8 * ((NCHUNK - 1) % STAGES), ((NCHUNK - 1) / STAGES) & 1);
    TC_FENCE_AFTER();

    // Epilogue (FP32 OUTPUT): warp reads its 32-lane subpartition (row =
    // wid*32+lid). Reference semantics: bf16(acc) + bf16(bias) in bf16 -> f32.
    {
        int mrow = m0 + wid * 32 + lid;
        float* orow = out + (size_t)mrow * Ndim + n0;
        #pragma unroll
        for (int cb = 0; cb < NT; cb += 32) {
            uint32_t r[32];
            LDTM_X32(r, tmem + cb);
            TC_WAIT_LD();
            float vals[32];
            #pragma unroll
            for (int j = 0; j < 32; j++) {
                __nv_bfloat16 s = __hadd(__float2bfloat16(__uint_as_float(r[j])),
                                         __float2bfloat16(bias[n0 + cb + j]));
                vals[j] = __bfloat162float(s);
            }
            float4* dst = reinterpret_cast<float4*>(orow + cb);
            #pragma unroll
            for (int q = 0; q < 8; q++) {
                dst[q] = make_float4(vals[4 * q], vals[4 * q + 1],
                                     vals[4 * q + 2], vals[4 * q + 3]);
            }
        }
    }

    __syncthreads();
    if (tid == 0) {
        #pragma unroll
        for (int s = 0; s < STAGES; s++) mbar_inval(sb + SMEM_MBAR + 8 * s);
    }
    __syncthreads();
    if (wid == 0) {
        TC_RELINQUISH();
        TC_DEALLOC(tmem, 128);
    }
#else
    // ---------- Generic fallback (no tcgen05 in this compile pass) ----------
    __nv_bfloat16* As = reinterpret_cast<__nv_bfloat16*>(smem);            // 128 x 32
    __nv_bfloat16* Bs = As + 128 * 32;                                     // 128 x 32
    int tr = tid >> 3;   // 0..15 -> rows [tr*8, tr*8+8)
    int tc = tid & 7;    // 0..7  -> cols [tc*16, tc*16+16)

    float acc[8][16];
    #pragma unroll
    for (int i = 0; i < 8; i++)
        #pragma unroll
        for (int j = 0; j < 16; j++) acc[i][j] = 0.0f;

    for (int kc = 0; kc < Kdim; kc += 32) {
        const uint4* srcA = reinterpret_cast<const uint4*>(g_x + (size_t)(m0 + tid) * Kdim + kc);
        const uint4* srcB = reinterpret_cast<const uint4*>(g_w + (size_t)(n0 + tid) * Kdim + kc);
        uint4* dA = reinterpret_cast<uint4*>(As + tid * 32);
        uint4* dB = reinterpret_cast<uint4*>(Bs + tid * 32);
        #pragma unroll
        for (int j = 0; j < 4; j++) { dA[j] = srcA[j]; dB[j] = srcB[j]; }
        __syncthreads();

        for (int kk = 0; kk < 32; kk++) {
            float a[8], b[16];
            #pragma unroll
            for (int i = 0; i < 8; i++)
                a[i] = __bfloat162float(As[(tr * 8 + i) * 32 + kk]);
            #pragma unroll
            for (int j = 0; j < 16; j++)
                b[j] = __bfloat162float(Bs[(tc * 16 + j) * 32 + kk]);
            #pragma unroll
            for (int i = 0; i < 8; i++)
                #pragma unroll
                for (int j = 0; j < 16; j++)
                    acc[i][j] = fmaf(a[i], b[j], acc[i][j]);
        }
        __syncthreads();
    }

    #pragma unroll
    for (int i = 0; i < 8; i++) {
        int m = m0 + tr * 8 + i;
        #pragma unroll
        for (int j = 0; j < 16; j++) {
            int n = n0 + tc * 16 + j;
            __nv_bfloat16 v = __hadd(__float2bfloat16(acc[i][j]),
                                     __float2bfloat16(bias[n]));
            out[(size_t)m * Ndim + n] = __bfloat162float(v);
        }
    }
#endif
}

// ============================================================================
// Launch
// ============================================================================

extern "C" void kernel_launch(void* const* d_in, const int* in_sizes, int n_in,
                              void* d_out, int out_size) {
    const float* x    = (const float*)d_in[0];   // [B, S, IN] f32
    const float* wq   = (const float*)d_in[1];   // [OUT, IN] f32 (fp8-representable)
    const float* ws   = (const float*)d_in[2];   // [OUT, 1] f32
    const float* bias = (const float*)d_in[3];   // [OUT] f32
    float* out = (float*)d_out;                  // [B, S, OUT] FP32

    // Convert inputs to bf16 scratch.
    {
        int threads = 256;
        int blocks = (Mdim * Kdim / 4) / threads;  // 16384
        cvt_x_kernel<<<blocks, threads>>>(x);
        cvt_w_kernel<<<blocks, threads>>>(wq, ws);
    }

    cudaFuncSetAttribute(gemm_kernel, cudaFuncAttributeMaxDynamicSharedMemorySize, SMEM_TOTAL);
    dim3 grid(Ndim / NT, Mdim / MT);  // (32, 32)
    gemm_kernel<<<grid, 128, SMEM_TOTAL>>>(out, bias);
}

// round 12
// speedup vs baseline: 2.8813x; 1.1478x over previous
#include <cuda_runtime.h>
#include <cuda_bf16.h>
#include <cstdint>

// ============================================================================
// out_f32[m, n] = f32( bf16(sum_k bf16(x[m,k]) * (bf16(w_fp8[n,k])*bf16(sc[n]))) + bf16(bias[n]) )
// M = B*S = 4096, N = OUT = 4096, K = IN = 4096. OUTPUT FP32.
// R11 was L2-bandwidth-bound (2 GB L2->SM @ ~80% of LTS cap). This round:
// cta_group::2 MMA with cluster (2,1,1): 256x256 tile per CTA-pair, same
// 32 KB/chunk load per CTA -> chip L2 traffic halves to 1 GB.
//   - CTA rank r loads A rows m0+r*128.. and B N-rows n0+r*128.. (B split per
//     the validated test_2cta_mma_bf16 semantics).
//   - Per chunk: both CTAs arrive full[s] (count=2) on rank0; rank0 issues
//     4 x (K=16, N=256, M=256) cg2 SS dispatches; commit multicasts to both
//     CTAs' empty[s]; lag-1 buffer-reuse gate on empty[s].
// tcgen05 only in the arch-specific pass; generic pass gets a scalar fallback.
// ============================================================================

#if defined(__CUDA_ARCH__) && \
    (defined(__CUDA_ARCH_FEAT_SM103_ALL) || defined(__CUDA_ARCH_FEAT_SM100_ALL) || \
     defined(__CUDA_ARCH_FEAT_SM101_ALL) || defined(__CUDA_ARCH_SPECIFIC__) || \
     defined(__CUDA_ARCH_FAMILY_SPECIFIC__))
#define HAS_TCGEN05 1
#else
#define HAS_TCGEN05 0
#endif

static constexpr int Mdim = 4096, Ndim = 4096, Kdim = 4096;
static constexpr int MT = 256, NT = 256, KC = 64;        // pair tile; KC=64 bf16=128B
static constexpr int STAGES = 3;
static constexpr int NCHUNK = Kdim / KC;                  // 64
static constexpr int STAGE_BYTES = 128 * 128;             // 128 rows x 128B per CTA

static constexpr int SMEM_TMEM_PTR = 0;
static constexpr int SMEM_EMPTY = 64;                     // 3 x 8B (commit multicast)
static constexpr int SMEM_FULL = 96;                      // 3 x 8B (rank0, count=2)
static constexpr int SMEM_A = 1024;
static constexpr int SMEM_B = SMEM_A + STAGES * STAGE_BYTES;
static constexpr int SMEM_TOTAL = SMEM_B + STAGES * STAGE_BYTES;  // ~99.3 KB -> 2 CTAs/SM

// idesc kind::f16 cg2: dtype=F32(1<<4), atype=BF16(1<<7), btype=BF16(1<<10),
// N=256 -> (256/8)<<17, M=256 -> (256/16)<<24  (matches test_2cta_mma_bf16)
static constexpr uint32_t IDESC_CG2 =
    (1u << 4) | (1u << 7) | (1u << 10) | ((NT / 8) << 17) | ((MT / 16) << 24);

// bf16 scratch (allowed: __device__ global arrays)
__device__ __nv_bfloat16 g_x[(size_t)Mdim * Kdim];
__device__ __nv_bfloat16 g_w[(size_t)Ndim * Kdim];

// ============================================================================
// PTX helpers
// ============================================================================

__device__ __forceinline__ uint32_t smem_u32(const void* p) {
    uint32_t a;
    asm("{ .reg .u64 t; cvta.to.shared.u64 t, %1; cvt.u32.u64 %0, t; }"
        : "=r"(a) : "l"(p));
    return a;
}

__device__ __forceinline__ uint32_t ctarank() {
    uint32_t r;
    asm("mov.u32 %0, %%cluster_ctarank;" : "=r"(r));
    return r;
}

__device__ __forceinline__ void cluster_sync() {
    asm volatile("barrier.cluster.arrive.aligned;" ::: "memory");
    asm volatile("barrier.cluster.wait.aligned;" ::: "memory");
}

__device__ __forceinline__ void cp_async16(uint32_t s, const void* g) {
    asm volatile("cp.async.cg.shared.global [%0], [%1], 16;" :: "r"(s), "l"(g));
}
__device__ __forceinline__ void cp_commit() {
    asm volatile("cp.async.commit_group;" ::: "memory");
}
template <int N>
__device__ __forceinline__ void cp_wait() {
    asm volatile("cp.async.wait_group %0;" :: "n"(N) : "memory");
}

#if HAS_TCGEN05
__device__ __forceinline__ uint32_t elect_one() {
    uint32_t pred;
    asm volatile(
        "{\n\t.reg .pred p;\n\t"
        "elect.sync _|p, 0xFFFFFFFF;\n\t"
        "selp.b32 %0, 1, 0, p;\n\t}"
        : "=r"(pred));
    return pred;
}

__device__ __forceinline__ void mbar_init(uint32_t addr, uint32_t count) {
    asm volatile("mbarrier.init.shared.b64 [%0], %1;" :: "r"(addr), "r"(count) : "memory");
}
__device__ __forceinline__ void mbar_inval(uint32_t addr) {
    asm volatile("mbarrier.inval.shared.b64 [%0];" :: "r"(addr) : "memory");
}
__device__ __forceinline__ void mbar_wait(uint32_t addr, uint32_t parity) {
    asm volatile(
        "{\n\t.reg .pred P;\n\t"
        "WAIT_%=:\n\t"
        "mbarrier.try_wait.parity.acquire.cta.shared::cta.b64 P, [%0], %1, 0x989680;\n\t"
        "@P bra DONE_%=;\n\t"
        "bra WAIT_%=;\n\t"
        "DONE_%=:\n\t}"
        :: "r"(addr), "r"(parity) : "memory");
}

__device__ __forceinline__ void mbar_wait_cluster(uint32_t addr, uint32_t parity) {
    asm volatile(
        "{\n\t.reg .pred P;\n\t"
        "WAIT_%=:\n\t"
        "mbarrier.try_wait.parity.acquire.cluster.shared::cta.b64 P, [%0], %1, 0x989680;\n\t"
        "@P bra DONE_%=;\n\t"
        "bra WAIT_%=;\n\t"
        "DONE_%=:\n\t}"
        :: "r"(addr), "r"(parity) : "memory");
}

// Arrive on the mbarrier at the same SMEM offset in cluster CTA `target_rank`.
__device__ __forceinline__ void mbar_arrive_cluster(uint32_t local_addr, uint32_t target_rank) {
    asm volatile(
        "{\n\t.reg .b32 ra;\n\t"
        "mapa.shared::cluster.u32 ra, %0, %1;\n\t"
        "mbarrier.arrive.shared::cluster.b64 _, [ra];\n\t}"
        :: "r"(local_addr), "r"(target_rank) : "memory");
}

__device__ __forceinline__ void fence_proxy_async_cta() {
    asm volatile("fence.proxy.async.shared::cta;" ::: "memory");
}

// SW128 K-major descriptor: layout=2, version=1, SBO=64, LBO=1
__device__ __forceinline__ uint64_t make_desc(uint32_t addr) {
    const uint64_t base =
        (uint64_t(2) << 61) | (uint64_t(1) << 46) | (uint64_t(64) << 32) | (uint64_t(1) << 16);
    return base | ((uint64_t)(addr >> 4) & 0x3FFF);
}

// cg2 bf16 SS MMA (form from test_2cta_mma_bf16)
__device__ __forceinline__ void mma_f16_ss_cg2(uint32_t d_tmem, uint64_t a_desc,
                                               uint64_t b_desc, uint32_t idesc,
                                               uint32_t enable) {
    asm volatile(
        "{\n\t.reg .pred p;\n\t"
        "setp.ne.u32 p, %6, 0;\n\t"
        "tcgen05.mma.cta_group::2.kind::f16 [%0], %1, %2, %3, "
        "{%4, %4, %4, %4, %4, %4, %4, %4}, p;\n\t}"
        :: "r"(d_tmem), "l"(a_desc), "l"(b_desc), "r"(idesc),
           "r"(0u), "r"(0u), "r"(enable)
        : "memory");
}

__device__ __forceinline__ void tc_commit_mcast_cg2(uint32_t mbar, uint16_t mask) {
    asm volatile(
        "tcgen05.commit.cta_group::2.mbarrier::arrive::one.shared::cluster.multicast::cluster.b64 [%0], %1;"
        :: "r"(mbar), "h"(mask) : "memory");
}

#define TC_ALLOC_CG2(smem_addr, ncols) \
    asm volatile("tcgen05.alloc.cta_group::2.sync.aligned.shared::cta.b32 [%0], %1;" \
                 :: "r"(smem_addr), "r"((uint32_t)(ncols)) : "memory")
#define TC_DEALLOC_CG2(tmem, ncols) \
    asm volatile("tcgen05.dealloc.cta_group::2.sync.aligned.b32 %0, %1;" \
                 :: "r"(tmem), "r"((uint32_t)(ncols)))
#define TC_RELINQUISH_CG2() \
    asm volatile("tcgen05.relinquish_alloc_permit.cta_group::2.sync.aligned;")
#define TC_FENCE_AFTER() asm volatile("tcgen05.fence::after_thread_sync;" ::: "memory")
#define TC_WAIT_LD() asm volatile("tcgen05.wait::ld.sync.aligned;" ::: "memory")

#define LDTM_X32(r, addr) \
    asm volatile( \
        "tcgen05.ld.sync.aligned.32x32b.x32.b32 " \
        "{%0, %1, %2, %3, %4, %5, %6, %7, " \
        " %8, %9, %10, %11, %12, %13, %14, %15, " \
        " %16, %17, %18, %19, %20, %21, %22, %23, " \
        " %24, %25, %26, %27, %28, %29, %30, %31}, [%32];" \
        : "=r"((r)[0]),  "=r"((r)[1]),  "=r"((r)[2]),  "=r"((r)[3]), \
          "=r"((r)[4]),  "=r"((r)[5]),  "=r"((r)[6]),  "=r"((r)[7]), \
          "=r"((r)[8]),  "=r"((r)[9]),  "=r"((r)[10]), "=r"((r)[11]), \
          "=r"((r)[12]), "=r"((r)[13]), "=r"((r)[14]), "=r"((r)[15]), \
          "=r"((r)[16]), "=r"((r)[17]), "=r"((r)[18]), "=r"((r)[19]), \
          "=r"((r)[20]), "=r"((r)[21]), "=r"((r)[22]), "=r"((r)[23]), \
          "=r"((r)[24]), "=r"((r)[25]), "=r"((r)[26]), "=r"((r)[27]), \
          "=r"((r)[28]), "=r"((r)[29]), "=r"((r)[30]), "=r"((r)[31]) \
        : "r"(addr))
#endif  // HAS_TCGEN05

// ============================================================================
// Conversion kernels (arch-neutral)
// ============================================================================

__global__ void __launch_bounds__(256) cvt_x_kernel(const float* __restrict__ x) {
    size_t i = ((size_t)blockIdx.x * blockDim.x + threadIdx.x) * 4;
    float4 v = *reinterpret_cast<const float4*>(x + i);
    *reinterpret_cast<__nv_bfloat162*>(&g_x[i])     = __floats2bfloat162_rn(v.x, v.y);
    *reinterpret_cast<__nv_bfloat162*>(&g_x[i + 2]) = __floats2bfloat162_rn(v.z, v.w);
}

__global__ void __launch_bounds__(256) cvt_w_kernel(const float* __restrict__ wq,
                                                    const float* __restrict__ sc) {
    size_t i = ((size_t)blockIdx.x * blockDim.x + threadIdx.x) * 4;
    int o = (int)(i >> 12);  // row = i / 4096
    __nv_bfloat16 s = __float2bfloat16(sc[o]);
    float4 v = *reinterpret_cast<const float4*>(wq + i);
    __nv_bfloat16 h0 = __hmul(__float2bfloat16(v.x), s);
    __nv_bfloat16 h1 = __hmul(__float2bfloat16(v.y), s);
    __nv_bfloat16 h2 = __hmul(__float2bfloat16(v.z), s);
    __nv_bfloat16 h3 = __hmul(__float2bfloat16(v.w), s);
    *reinterpret_cast<__nv_bfloat162*>(&g_w[i])     = __halves2bfloat162(h0, h1);
    *reinterpret_cast<__nv_bfloat162*>(&g_w[i + 2]) = __halves2bfloat162(h2, h3);
}

// ============================================================================
// GEMM kernel: 256x256 tile per CTA pair (cg2), coalesced cp.async, lag-1.
// ============================================================================

__global__ void __launch_bounds__(128) __cluster_dims__(2, 1, 1)
gemm_kernel(float* __restrict__ out, const float* __restrict__ bias) {
    extern __shared__ char smem[];
    int tid = threadIdx.x;

#if HAS_TCGEN05
    uint32_t sb = smem_u32(smem);
    int wid = tid >> 5;
    int lid = tid & 31;
    uint32_t rank = ctarank();
    int n0t = (blockIdx.x >> 1) * NT;          // pair's N origin
    int m0t = blockIdx.y * MT;                 // pair's M origin

    if (tid == 0) {
        #pragma unroll
        for (int s = 0; s < STAGES; s++) {
            mbar_init(sb + SMEM_EMPTY + 8 * s, 1);   // commit multicast arrival
            mbar_init(sb + SMEM_FULL + 8 * s, 2);    // both CTAs arrive (rank0's used)
        }
    }
    if (wid == 0) {
        TC_ALLOC_CG2(sb + SMEM_TMEM_PTR, 256);
    }
    __syncthreads();
    uint32_t tmem;
    asm volatile("ld.shared.b32 %0, [%1];" : "=r"(tmem) : "r"(sb + SMEM_TMEM_PTR));

    // All mbarriers (esp. rank0's full[]) must be init'd cluster-wide before use.
    cluster_sync();

    // COALESCED load mapping: 8 lanes per 128B row; pass j covers rows j*16..+16.
    int lrow = tid >> 3;
    int lcolb = (tid & 7) * 16;
    uint32_t swc[8];
    #pragma unroll
    for (int j = 0; j < 8; j++) {
        uint32_t off = (uint32_t)(lrow + j * 16) * 128 + lcolb;
        swc[j] = off ^ ((off >> 3) & 0x70);
    }
    // This CTA's halves: A rows m0t + rank*128 + [0,128); B N-rows n0t + rank*128 + [0,128).
    const __nv_bfloat16* xbase =
        g_x + (size_t)(m0t + rank * 128 + lrow) * Kdim + (tid & 7) * 8;
    const __nv_bfloat16* wbase =
        g_w + (size_t)(n0t + rank * 128 + lrow) * Kdim + (tid & 7) * 8;

    auto load_chunk = [&](int c, int s) {
        uint32_t abase = sb + SMEM_A + s * STAGE_BYTES;
        uint32_t bbase = sb + SMEM_B + s * STAGE_BYTES;
        const __nv_bfloat16* xa = xbase + c * KC;
        const __nv_bfloat16* wb = wbase + c * KC;
        #pragma unroll
        for (int j = 0; j < 8; j++) {
            cp_async16(abase + swc[j], xa + (size_t)j * 16 * Kdim);
            cp_async16(bbase + swc[j], wb + (size_t)j * 16 * Kdim);
        }
        cp_commit();
    };

    // Prologue: prefetch chunks 0 and 1.
    load_chunk(0, 0);
    load_chunk(1, 1);

    for (int c = 0; c < NCHUNK; c++) {
        int buf = c % STAGES;

        // Lag-1 reuse gate: before overwriting buffer (c+2)%3 == (c-1)%3, wait
        // for chunk c-1's commit (multicast delivered to BOTH CTAs' empty[]).
        if (c + 2 < NCHUNK) {
            if (c >= 1) {
                mbar_wait(sb + SMEM_EMPTY + 8 * ((c - 1) % STAGES), ((c - 1) / STAGES) & 1);
            }
            load_chunk(c + 2, (c + 2) % STAGES);
        }

        // Wait for chunk c's cp.async group (2 newer groups may be pending).
        int rem = NCHUNK - 1 - c;
        if (rem >= 2)      cp_wait<2>();
        else if (rem == 1) cp_wait<1>();
        else               cp_wait<0>();
        fence_proxy_async_cta();
        __syncthreads();

        // Signal this CTA's stage is ready: arrive on rank0's full[buf] (count=2).
        if (tid == 0) {
            mbar_arrive_cluster(sb + SMEM_FULL + 8 * buf, 0);
        }

        // Rank 0 issues the cg2 MMAs once both CTAs have arrived.
        if (rank == 0 && wid == 0) {
            if (elect_one()) {
                mbar_wait_cluster(sb + SMEM_FULL + 8 * buf, (c / STAGES) & 1);
                TC_FENCE_AFTER();
                uint64_t ad = make_desc(sb + SMEM_A + buf * STAGE_BYTES);
                uint64_t bd = make_desc(sb + SMEM_B + buf * STAGE_BYTES);
                #pragma unroll
                for (int kk = 0; kk < 4; kk++) {
                    // K-step: 16 bf16 = 32B = 2 descriptor units. M=256,N=256 cg2.
                    mma_f16_ss_cg2(tmem, ad + kk * 2, bd + kk * 2, IDESC_CG2,
                                   (c == 0 && kk == 0) ? 0u : 1u);
                }
                tc_commit_mcast_cg2(sb + SMEM_EMPTY + 8 * buf, 0x3);
            }
        }
    }

    // Final commit (chunk NCHUNK-1) tracks all prior MMAs; delivered to both CTAs.
    mbar_wait(sb + SMEM_EMPTY + 8 * ((NCHUNK - 1) % STAGES), ((NCHUNK - 1) / STAGES) & 1);
    TC_FENCE_AFTER();

    // Epilogue (FP32): each CTA's TMEM holds D rows [rank*128, rank*128+128) of
    // the 256-row tile, all 256 cols. Row = rank*128 + wid*32 + lid.
    {
        int mrow = m0t + (int)rank * 128 + wid * 32 + lid;
        float* orow = out + (size_t)mrow * Ndim + n0t;
        #pragma unroll
        for (int cb = 0; cb < NT; cb += 32) {
            uint32_t r[32];
            LDTM_X32(r, tmem + cb);
            TC_WAIT_LD();
            float vals[32];
            #pragma unroll
            for (int j = 0; j < 32; j++) {
                __nv_bfloat16 s = __hadd(__float2bfloat16(__uint_as_float(r[j])),
                                         __float2bfloat16(bias[n0t + cb + j]));
                vals[j] = __bfloat162float(s);
            }
            float4* dst = reinterpret_cast<float4*>(orow + cb);
            #pragma unroll
            for (int q = 0; q < 8; q++) {
                dst[q] = make_float4(vals[4 * q], vals[4 * q + 1],
                                     vals[4 * q + 2], vals[4 * q + 3]);
            }
        }
    }

    __syncthreads();
    if (tid == 0) {
        #pragma unroll
        for (int s = 0; s < STAGES; s++) {
            mbar_inval(sb + SMEM_EMPTY + 8 * s);
            mbar_inval(sb + SMEM_FULL + 8 * s);
        }
    }
    __syncthreads();
    if (wid == 0) {
        TC_RELINQUISH_CG2();
        TC_DEALLOC_CG2(tmem, 256);
    }
    cluster_sync();
#else
    // ---------- Generic fallback (no tcgen05 in this compile pass) ----------
    int rank = blockIdx.x & 1;
    int n0t = (blockIdx.x >> 1) * NT;
    int m0 = blockIdx.y * MT + rank * 128;

    for (int half = 0; half < 2; half++) {
        int n0 = n0t + half * 128;
        __nv_bfloat16* As = reinterpret_cast<__nv_bfloat16*>(smem);        // 128 x 32
        __nv_bfloat16* Bs = As + 128 * 32;                                 // 128 x 32
        int tr = tid >> 3;
        int tc = tid & 7;

        float acc[8][16];
        #pragma unroll
        for (int i = 0; i < 8; i++)
            #pragma unroll
            for (int j = 0; j < 16; j++) acc[i][j] = 0.0f;

        for (int kc = 0; kc < Kdim; kc += 32) {
            const uint4* srcA = reinterpret_cast<const uint4*>(g_x + (size_t)(m0 + tid) * Kdim + kc);
            const uint4* srcB = reinterpret_cast<const uint4*>(g_w + (size_t)(n0 + tid) * Kdim + kc);
            uint4* dA = reinterpret_cast<uint4*>(As + tid * 32);
            uint4* dB = reinterpret_cast<uint4*>(Bs + tid * 32);
            #pragma unroll
            for (int j = 0; j < 4; j++) { dA[j] = srcA[j]; dB[j] = srcB[j]; }
            __syncthreads();

            for (int kk = 0; kk < 32; kk++) {
                float a[8], b[16];
                #pragma unroll
                for (int i = 0; i < 8; i++)
                    a[i] = __bfloat162float(As[(tr * 8 + i) * 32 + kk]);
                #pragma unroll
                for (int j = 0; j < 16; j++)
                    b[j] = __bfloat162float(Bs[(tc * 16 + j) * 32 + kk]);
                #pragma unroll
                for (int i = 0; i < 8; i++)
                    #pragma unroll
                    for (int j = 0; j < 16; j++)
                        acc[i][j] = fmaf(a[i], b[j], acc[i][j]);
            }
            __syncthreads();
        }

        #pragma unroll
        for (int i = 0; i < 8; i++) {
            int m = m0 + tr * 8 + i;
            #pragma unroll
            for (int j = 0; j < 16; j++) {
                int n = n0 + tc * 16 + j;
                __nv_bfloat16 v = __hadd(__float2bfloat16(acc[i][j]),
                                         __float2bfloat16(bias[n]));
                out[(size_t)m * Ndim + n] = __bfloat162float(v);
            }
        }
        __syncthreads();
    }
#endif
}

// ============================================================================
// Launch
// ============================================================================

extern "C" void kernel_launch(void* const* d_in, const int* in_sizes, int n_in,
                              void* d_out, int out_size) {
    const float* x    = (const float*)d_in[0];   // [B, S, IN] f32
    const float* wq   = (const float*)d_in[1];   // [OUT, IN] f32 (fp8-representable)
    const float* ws   = (const float*)d_in[2];   // [OUT, 1] f32
    const float* bias = (const float*)d_in[3];   // [OUT] f32
    float* out = (float*)d_out;                  // [B, S, OUT] FP32

    // Convert inputs to bf16 scratch.
    {
        int threads = 256;
        int blocks = (Mdim * Kdim / 4) / threads;  // 16384
        cvt_x_kernel<<<blocks, threads>>>(x);
        cvt_w_kernel<<<blocks, threads>>>(wq, ws);
    }

    cudaFuncSetAttribute(gemm_kernel, cudaFuncAttributeMaxDynamicSharedMemorySize, SMEM_TOTAL);
    // Grid: x = 2 CTAs/pair * 16 n-tiles = 32, y = 16 m-tiles; cluster (2,1,1).
    dim3 grid(2 * (Ndim / NT), Mdim / MT);  // (32, 16)
    gemm_kernel<<<grid, 128, SMEM_TOTAL>>>(out, bias);
}